// round 7
// baseline (speedup 1.0000x reference)
#include <cuda_runtime.h>
#include <cstdint>

// S4D kernel generation as 1024 per-CTA bf16 HMMA GEMMs.
//   l = 32u + v, u in [0,128), v in [0,32)
//   K[h,l] = sum_{m<64} F[u,m] * G[v,m]
// R7: prologue critical path cut ~2.5x — B power loop split across 4 v-groups
// (8 steps instead of 32), T2/U tables split across 4 warps, discretization
// redundant per warp. MMA mainloop/epilogue identical to R6 (verified).

#define HN  1024
#define NM  32
#define LL  4096
#define TPB 128

__device__ __forceinline__ uint32_t pack_hi16(float a, float b) {
    uint32_t r;
    asm("prmt.b32 %0, %1, %2, 0x7632;"
        : "=r"(r) : "r"(__float_as_uint(a)), "r"(__float_as_uint(b)));
    return r;
}

__device__ __forceinline__ void mma16816(float* c, uint32_t a0, uint32_t a1,
                                         uint32_t a2, uint32_t a3,
                                         uint32_t b0, uint32_t b1) {
    asm volatile(
        "mma.sync.aligned.m16n8k16.row.col.f32.bf16.bf16.f32 "
        "{%0,%1,%2,%3}, {%4,%5,%6,%7}, {%8,%9}, {%0,%1,%2,%3};"
        : "+f"(c[0]), "+f"(c[1]), "+f"(c[2]), "+f"(c[3])
        : "r"(a0), "r"(a1), "r"(a2), "r"(a3), "r"(b0), "r"(b1));
}

// fragment-major word offset, 8-row x 4-wordcol micro-tiles
#define WOFF(r, c) ((((r) >> 3) << 8) + ((((c) >> 2)) << 5) + (((r) & 7) << 2) + ((c) & 3))

struct Cx { float r, i; };
__device__ __forceinline__ Cx cmul(Cx a, Cx b) {
    return { a.r * b.r - a.i * b.i, a.r * b.i + a.i * b.r };
}
__device__ __forceinline__ Cx csq(Cx a) {
    return { a.r * a.r - a.i * a.i, 2.0f * a.r * a.i };
}

__global__ void __launch_bounds__(TPB)
s4d_hmma_kernel(const float* __restrict__ log_dt,      // (H)
                const float* __restrict__ C_real,      // (1,H,NM,2)
                const float* __restrict__ log_A_real,  // (H,NM)
                const float* __restrict__ A_imag,      // (H,NM)
                float* __restrict__ out)               // (1,H,L)
{
    __shared__ uint32_t sAh[128 * 32], sAl[128 * 32];   // 16 KB each
    __shared__ uint16_t sBh[32 * 64], sBl[32 * 64];     // 4 KB each
    __shared__ float T2r[16][33], T2i[16][33];          // Z^b, Z = dA^32
    __shared__ float Ur[8][33],  Ui[8][33];             // 2*dC * Z^(16a)

    const int h = blockIdx.x;
    const int t = threadIdx.x;
    const int m = t & 31;       // mode
    const int g = t >> 5;       // group / warp id

    // ---- Discretization (all threads, redundant across warps -> no cross-warp dep)
    {
        const float dt  = expf(log_dt[h]);
        const float Aor = -expf(log_A_real[h * NM + m]);
        const float Aoi = A_imag[h * NM + m];
        const float dtAr = Aor * dt, dtAi = Aoi * dt;
        const float denr = 1.0f - 0.5f * dtAr;
        const float deni = -0.5f * dtAi;
        const float inv  = 1.0f / (denr * denr + deni * deni);
        const float Br = dt * denr * inv;
        const float Bi = -dt * deni * inv;
        const float Cr = C_real[(h * NM + m) * 2 + 0];
        const float Ci = C_real[(h * NM + m) * 2 + 1];
        const Cx dC = { 2.0f * (Cr * Br - Ci * Bi),     // factor 2 baked in
                        2.0f * (Cr * Bi + Ci * Br) };
        const float numr = 1.0f + 0.5f * dtAr;
        const float numi = 0.5f * dtAi;
        const Cx dA = { (numr * denr + numi * deni) * inv,
                        (numi * denr - numr * deni) * inv };

        // ---- power ladder shared by B-gen and tables
        const Cx c2  = csq(dA);
        const Cx c4  = csq(c2);
        const Cx c8  = csq(c4);
        const Cx c16 = csq(c8);

        // ---- B tile: this thread covers v in [8g, 8g+8), mode m
        {
            Cx w;
            if (g == 0)      w = {1.0f, 0.0f};
            else if (g == 1) w = c8;
            else if (g == 2) w = c16;
            else             w = cmul(c16, c8);
            const int cRe = m >> 1, cIm = 16 + (m >> 1), half = m & 1;
            #pragma unroll
            for (int i = 0; i < 8; ++i) {
                const int v = 8 * g + i;
                const int iRe = (WOFF(v, cRe) << 1) + half;
                const int iIm = (WOFF(v, cIm) << 1) + half;
                const uint32_t xr = __float_as_uint(w.r);
                const float hr = __uint_as_float(xr & 0xFFFF0000u);
                sBh[iRe] = (uint16_t)(xr >> 16);
                sBl[iRe] = (uint16_t)(__float_as_uint(w.r - hr) >> 16);
                const float niv = -w.i;
                const uint32_t xi = __float_as_uint(niv);
                const float hi = __uint_as_float(xi & 0xFFFF0000u);
                sBh[iIm] = (uint16_t)(xi >> 16);
                sBl[iIm] = (uint16_t)(__float_as_uint(niv - hi) >> 16);
                w = cmul(w, dA);
            }
        }

        // ---- T2 slice: T2[b] = Z^b for b in [4g, 4g+4), Z = dA^32
        const Cx Z  = csq(c16);
        const Cx Z2 = csq(Z);
        const Cx Z4 = csq(Z2);
        const Cx Z8 = csq(Z4);
        {
            Cx p;
            if (g == 0)      p = {1.0f, 0.0f};
            else if (g == 1) p = Z4;
            else if (g == 2) p = Z8;
            else             p = cmul(Z8, Z4);
            #pragma unroll
            for (int i = 0; i < 4; ++i) {
                T2r[4 * g + i][m] = p.r;
                T2i[4 * g + i][m] = p.i;
                p = cmul(p, Z);
            }
        }
        // ---- U slice: U[a] = dC * Z16^a for a in {2g, 2g+1}
        const Cx Z16 = csq(Z8);
        const Cx Z32 = csq(Z16);
        {
            Cx y;
            if (g == 0)      y = dC;
            else if (g == 1) y = cmul(dC, Z32);
            else if (g == 2) y = cmul(dC, csq(Z32));
            else             y = cmul(dC, cmul(csq(Z32), Z32));
            Ur[2 * g][m] = y.r; Ui[2 * g][m] = y.i;
            y = cmul(y, Z16);
            Ur[2 * g + 1][m] = y.r; Ui[2 * g + 1][m] = y.i;
        }
    }
    __syncthreads();

    // ---- A tiles: thread t = row u. P = U[u>>4] * T2[u&15].
    {
        const int aI = t >> 4, bI = t & 15;
        #pragma unroll
        for (int j = 0; j < 16; ++j) {
            const int n0 = 2 * j, n1 = 2 * j + 1;
            const float u0r = Ur[aI][n0], u0i = Ui[aI][n0];
            const float t0r = T2r[bI][n0], t0i = T2i[bI][n0];
            const float p0r = u0r * t0r - u0i * t0i;
            const float p0i = u0r * t0i + u0i * t0r;
            const float u1r = Ur[aI][n1], u1i = Ui[aI][n1];
            const float t1r = T2r[bI][n1], t1i = T2i[bI][n1];
            const float p1r = u1r * t1r - u1i * t1i;
            const float p1i = u1r * t1i + u1i * t1r;
            const float h0r = __uint_as_float(__float_as_uint(p0r) & 0xFFFF0000u);
            const float h1r = __uint_as_float(__float_as_uint(p1r) & 0xFFFF0000u);
            const float h0i = __uint_as_float(__float_as_uint(p0i) & 0xFFFF0000u);
            const float h1i = __uint_as_float(__float_as_uint(p1i) & 0xFFFF0000u);
            const int wRe = WOFF(t, j);        // K cols 2j, 2j+1 (Re)
            const int wIm = WOFF(t, 16 + j);   // K cols 32+2j   (Im)
            sAh[wRe] = pack_hi16(p0r, p1r);
            sAh[wIm] = pack_hi16(p0i, p1i);
            sAl[wRe] = pack_hi16(p0r - h0r, p1r - h1r);
            sAl[wIm] = pack_hi16(p0i - h0i, p1i - h1i);
        }
    }
    __syncthreads();

    // ---- MMA mainloop: warp w -> rows [32w, 32w+32)
    const int lane = t & 31;
    const int wid  = t >> 5;
    const int gid  = lane >> 2;
    const int tig  = lane & 3;
    const int lbase = gid * 4 + tig;
    const int arow  = wid * 4;

    float acc[2][4][4] = {};

    const uint32_t* Aat[3] = { sAh, sAh, sAl };
    const uint32_t* Bat[3] = { (const uint32_t*)sBh, (const uint32_t*)sBl,
                               (const uint32_t*)sBh };

    #pragma unroll
    for (int s = 0; s < 3; ++s) {
        const uint32_t* A = Aat[s];
        const uint32_t* B = Bat[s];
        #pragma unroll
        for (int ks = 0; ks < 4; ++ks) {
            uint32_t b0[4], b1[4];
            #pragma unroll
            for (int nt = 0; nt < 4; ++nt) {
                const int w = nt * 256 + ks * 64 + lbase;
                b0[nt] = B[w];
                b1[nt] = B[w + 32];
            }
            #pragma unroll
            for (int mt = 0; mt < 2; ++mt) {
                const int w = (arow + mt * 2) * 256 + ks * 64 + lbase;
                const uint32_t a0 = A[w];
                const uint32_t a1 = A[w + 256];
                const uint32_t a2 = A[w + 32];
                const uint32_t a3 = A[w + 256 + 32];
                #pragma unroll
                for (int nt = 0; nt < 4; ++nt)
                    mma16816(acc[mt][nt], a0, a1, a2, a3, b0[nt], b1[nt]);
            }
        }
    }

    // ---- Epilogue
    float* __restrict__ o = out + (size_t)h * LL;
    const int r0 = wid * 32;
    #pragma unroll
    for (int mt = 0; mt < 2; ++mt) {
        const int u0 = r0 + mt * 16 + gid;
        #pragma unroll
        for (int nt = 0; nt < 4; ++nt) {
            const int v = nt * 8 + tig * 2;
            *reinterpret_cast<float2*>(o + (size_t)u0 * 32 + v) =
                make_float2(acc[mt][nt][0], acc[mt][nt][1]);
            *reinterpret_cast<float2*>(o + (size_t)(u0 + 8) * 32 + v) =
                make_float2(acc[mt][nt][2], acc[mt][nt][3]);
        }
    }
}

extern "C" void kernel_launch(void* const* d_in, const int* in_sizes, int n_in,
                              void* d_out, int out_size) {
    const float* log_dt     = (const float*)d_in[0];
    const float* C_real     = (const float*)d_in[1];
    const float* log_A_real = (const float*)d_in[2];
    const float* A_imag     = (const float*)d_in[3];
    float* out = (float*)d_out;
    s4d_hmma_kernel<<<HN, TPB>>>(log_dt, C_real, log_A_real, A_imag, out);
}

// round 8
// speedup vs baseline: 1.5691x; 1.5691x over previous
#include <cuda_runtime.h>
#include <cstdint>

// S4D kernel generation as 1024 per-CTA bf16 HMMA GEMMs.
//   l = 32u + v, u in [0,128), v in [0,32)
//   K[h,l] = sum_{m<64} F[u,m] * G[v,m]
// R8: A operands computed IN REGISTERS by the consuming thread (no A smem, no
// A-fill phase); Re/Im fragments share one cmul group. B re-laid out into
// per-lane 16B granules -> LDS.128 fragment loads. Prologue split warp0
// (tables) / warp1 (B-gen). Same split arithmetic as R6 -> same accuracy.

#define HN  1024
#define NM  32
#define LL  4096
#define TPB 128

__device__ __forceinline__ uint32_t pack_hi16(float a, float b) {
    uint32_t r;
    asm("prmt.b32 %0, %1, %2, 0x7632;"
        : "=r"(r) : "r"(__float_as_uint(a)), "r"(__float_as_uint(b)));
    return r;
}

__device__ __forceinline__ void mma16816(float* c, uint32_t a0, uint32_t a1,
                                         uint32_t a2, uint32_t a3,
                                         uint32_t b0, uint32_t b1) {
    asm volatile(
        "mma.sync.aligned.m16n8k16.row.col.f32.bf16.bf16.f32 "
        "{%0,%1,%2,%3}, {%4,%5,%6,%7}, {%8,%9}, {%0,%1,%2,%3};"
        : "+f"(c[0]), "+f"(c[1]), "+f"(c[2]), "+f"(c[3])
        : "r"(a0), "r"(a1), "r"(a2), "r"(a3), "r"(b0), "r"(b1));
}

struct Cx { float r, i; };
__device__ __forceinline__ Cx cmul(Cx a, Cx b) {
    return { a.r * b.r - a.i * b.i, a.r * b.i + a.i * b.r };
}
__device__ __forceinline__ Cx csq(Cx a) {
    return { a.r * a.r - a.i * a.i, 2.0f * a.r * a.i };
}

// B granule word index: word(v, wc) -> (wc>>2)*128 + ((v&7)*4 + (wc&3))*4 + (v>>3)
// Reader: granule (ks, h) at lane holds words nt=0..3 => one LDS.128.
#define BW(v, wc) (((wc) >> 2) * 128 + ((((v) & 7) << 2) + ((wc) & 3)) * 4 + ((v) >> 3))

__global__ void __launch_bounds__(TPB, 4)
s4d_hmma_kernel(const float* __restrict__ log_dt,      // (H)
                const float* __restrict__ C_real,      // (1,H,NM,2)
                const float* __restrict__ log_A_real,  // (H,NM)
                const float* __restrict__ A_imag,      // (H,NM)
                float* __restrict__ out)               // (1,H,L)
{
    __shared__ __align__(16) uint16_t sBh[2048], sBl[2048];  // 4 KB each
    __shared__ float T2r[16][33], T2i[16][33];               // Z^b, Z = dA^32
    __shared__ float Ur[8][33],  Ui[8][33];                  // 2*dC * Z^(16a)

    const int h    = blockIdx.x;
    const int t    = threadIdx.x;
    const int wid  = t >> 5;
    const int lane = t & 31;

    // ---- Prologue: warp0 -> tables, warp1 -> B tile (2x discretization only)
    if (wid < 2) {
        const int m = lane;
        const float dt  = expf(log_dt[h]);
        const float Aor = -expf(log_A_real[h * NM + m]);
        const float Aoi = A_imag[h * NM + m];
        const float dtAr = Aor * dt, dtAi = Aoi * dt;
        const float denr = 1.0f - 0.5f * dtAr;
        const float deni = -0.5f * dtAi;
        const float inv  = 1.0f / (denr * denr + deni * deni);
        const float Br = dt * denr * inv;
        const float Bi = -dt * deni * inv;
        const float Cr = C_real[(h * NM + m) * 2 + 0];
        const float Ci = C_real[(h * NM + m) * 2 + 1];
        const Cx dC = { 2.0f * (Cr * Br - Ci * Bi),      // factor 2 baked in
                        2.0f * (Cr * Bi + Ci * Br) };
        const float numr = 1.0f + 0.5f * dtAr;
        const float numi = 0.5f * dtAi;
        const Cx dA = { (numr * denr + numi * deni) * inv,
                        (numi * denr - numr * deni) * inv };

        if (wid == 1) {
            // B tile: G[v][m] = Re(dA^v), G[v][32+m] = -Im(dA^v); hi/lo split.
            const int wcR = m >> 1, wcI = 16 + (m >> 1), half = m & 1;
            Cx w = {1.0f, 0.0f};
            #pragma unroll 1
            for (int v = 0; v < 32; ++v) {
                const int iR = (BW(v, wcR) << 1) + half;
                const int iI = (BW(v, wcI) << 1) + half;
                const uint32_t xr = __float_as_uint(w.r);
                const float hr = __uint_as_float(xr & 0xFFFF0000u);
                sBh[iR] = (uint16_t)(xr >> 16);
                sBl[iR] = (uint16_t)(__float_as_uint(w.r - hr) >> 16);
                const float niv = -w.i;
                const uint32_t xi = __float_as_uint(niv);
                const float hi = __uint_as_float(xi & 0xFFFF0000u);
                sBh[iI] = (uint16_t)(xi >> 16);
                sBl[iI] = (uint16_t)(__float_as_uint(niv - hi) >> 16);
                w = cmul(w, dA);
            }
        } else {
            // Tables: Z = dA^32; T2[b] = Z^b; U[a] = 2dC * Z^(16a)
            Cx z = dA;
            #pragma unroll
            for (int j = 0; j < 5; ++j) z = csq(z);
            Cx p = {1.0f, 0.0f};
            #pragma unroll
            for (int b = 0; b < 16; ++b) {
                T2r[b][m] = p.r; T2i[b][m] = p.i;
                p = cmul(p, z);
            }
            const Cx z16 = p;           // Z^16
            Cx y = dC;
            #pragma unroll
            for (int a = 0; a < 8; ++a) {
                Ur[a][m] = y.r; Ui[a][m] = y.i;
                y = cmul(y, z16);
            }
        }
    }
    __syncthreads();

    // ---- Mainloop: warp w -> rows [32w, 32w+32); A fragments computed in-place.
    const int gid = lane >> 2;
    const int tig = lane & 3;

    float acc[2][4][4] = {};

    const float4* B4h = reinterpret_cast<const float4*>(sBh);
    const float4* B4l = reinterpret_cast<const float4*>(sBl);

    #pragma unroll
    for (int kq = 0; kq < 2; ++kq) {
        // modes for this thread: n0, n0+1, n0+8, n0+9
        const int n0 = 16 * kq + 2 * tig;

        // T2 rows gid (row r0) and gid+8 (row r1), 4 modes
        float tg_r[4], tg_i[4], th_r[4], th_i[4];
        #pragma unroll
        for (int j = 0; j < 4; ++j) {
            const int n = n0 + (j >> 1) * 8 + (j & 1);
            tg_r[j] = T2r[gid][n];     tg_i[j] = T2i[gid][n];
            th_r[j] = T2r[gid + 8][n]; th_i[j] = T2i[gid + 8][n];
        }

        // A fragments: [ksel(Re/Im)][hi/lo][mt][reg]
        uint32_t Af[2][2][2][4];
        #pragma unroll
        for (int mt = 0; mt < 2; ++mt) {
            const int a = wid * 2 + mt;
            float pr0[4], pi0[4], pr1[4], pi1[4];
            #pragma unroll
            for (int j = 0; j < 4; ++j) {
                const int n = n0 + (j >> 1) * 8 + (j & 1);
                const float ur = Ur[a][n], ui = Ui[a][n];
                pr0[j] = ur * tg_r[j] - ui * tg_i[j];
                pi0[j] = ur * tg_i[j] + ui * tg_r[j];
                pr1[j] = ur * th_r[j] - ui * th_i[j];
                pi1[j] = ur * th_i[j] + ui * th_r[j];
            }
            // hi words (truncation) + lo words (bf16 of residual)
            #pragma unroll
            for (int cp = 0; cp < 2; ++cp) {            // col-pair: j {0,1} / {2,3}
                const int j0 = cp * 2, j1 = cp * 2 + 1;
                Af[0][0][mt][cp * 2 + 0] = pack_hi16(pr0[j0], pr0[j1]); // reg a0/a2: row r0
                Af[0][0][mt][cp * 2 + 1] = pack_hi16(pr1[j0], pr1[j1]); // reg a1/a3: row r1
                Af[1][0][mt][cp * 2 + 0] = pack_hi16(pi0[j0], pi0[j1]);
                Af[1][0][mt][cp * 2 + 1] = pack_hi16(pi1[j0], pi1[j1]);
                const float d00 = pr0[j0] - __uint_as_float(__float_as_uint(pr0[j0]) & 0xFFFF0000u);
                const float d01 = pr0[j1] - __uint_as_float(__float_as_uint(pr0[j1]) & 0xFFFF0000u);
                const float d10 = pr1[j0] - __uint_as_float(__float_as_uint(pr1[j0]) & 0xFFFF0000u);
                const float d11 = pr1[j1] - __uint_as_float(__float_as_uint(pr1[j1]) & 0xFFFF0000u);
                Af[0][1][mt][cp * 2 + 0] = pack_hi16(d00, d01);
                Af[0][1][mt][cp * 2 + 1] = pack_hi16(d10, d11);
                const float e00 = pi0[j0] - __uint_as_float(__float_as_uint(pi0[j0]) & 0xFFFF0000u);
                const float e01 = pi0[j1] - __uint_as_float(__float_as_uint(pi0[j1]) & 0xFFFF0000u);
                const float e10 = pi1[j0] - __uint_as_float(__float_as_uint(pi1[j0]) & 0xFFFF0000u);
                const float e11 = pi1[j1] - __uint_as_float(__float_as_uint(pi1[j1]) & 0xFFFF0000u);
                Af[1][1][mt][cp * 2 + 0] = pack_hi16(e00, e01);
                Af[1][1][mt][cp * 2 + 1] = pack_hi16(e10, e11);
            }
        }

        // MMAs: ksel 0 -> ks=kq (Re cols), ksel 1 -> ks=kq+2 (Im cols)
        #pragma unroll
        for (int ksel = 0; ksel < 2; ++ksel) {
            const int ks = kq + 2 * ksel;
            const float4 bh0 = B4h[(ks * 2 + 0) * 32 + lane];
            const float4 bh1 = B4h[(ks * 2 + 1) * 32 + lane];
            const float4 bl0 = B4l[(ks * 2 + 0) * 32 + lane];
            const float4 bl1 = B4l[(ks * 2 + 1) * 32 + lane];
            const uint32_t* h0 = reinterpret_cast<const uint32_t*>(&bh0);
            const uint32_t* h1 = reinterpret_cast<const uint32_t*>(&bh1);
            const uint32_t* l0 = reinterpret_cast<const uint32_t*>(&bl0);
            const uint32_t* l1 = reinterpret_cast<const uint32_t*>(&bl1);
            #pragma unroll
            for (int mt = 0; mt < 2; ++mt) {
                const uint32_t* ah = Af[ksel][0][mt];
                const uint32_t* al = Af[ksel][1][mt];
                #pragma unroll
                for (int nt = 0; nt < 4; ++nt) {
                    mma16816(acc[mt][nt], ah[0], ah[1], ah[2], ah[3], h0[nt], h1[nt]); // Fh*Gh
                    mma16816(acc[mt][nt], ah[0], ah[1], ah[2], ah[3], l0[nt], l1[nt]); // Fh*Gl
                    mma16816(acc[mt][nt], al[0], al[1], al[2], al[3], h0[nt], h1[nt]); // Fl*Gh
                }
            }
        }
    }

    // ---- Epilogue (unchanged from R6)
    float* __restrict__ o = out + (size_t)h * LL;
    const int r0 = wid * 32;
    #pragma unroll
    for (int mt = 0; mt < 2; ++mt) {
        const int u0 = r0 + mt * 16 + gid;
        #pragma unroll
        for (int nt = 0; nt < 4; ++nt) {
            const int v = nt * 8 + tig * 2;
            *reinterpret_cast<float2*>(o + (size_t)u0 * 32 + v) =
                make_float2(acc[mt][nt][0], acc[mt][nt][1]);
            *reinterpret_cast<float2*>(o + (size_t)(u0 + 8) * 32 + v) =
                make_float2(acc[mt][nt][2], acc[mt][nt][3]);
        }
    }
}

extern "C" void kernel_launch(void* const* d_in, const int* in_sizes, int n_in,
                              void* d_out, int out_size) {
    const float* log_dt     = (const float*)d_in[0];
    const float* C_real     = (const float*)d_in[1];
    const float* log_A_real = (const float*)d_in[2];
    const float* A_imag     = (const float*)d_in[3];
    float* out = (float*)d_out;
    s4d_hmma_kernel<<<HN, TPB>>>(log_dt, C_real, log_A_real, A_imag, out);
}

// round 9
// speedup vs baseline: 1.6911x; 1.0778x over previous
#include <cuda_runtime.h>
#include <cstdint>

// S4D kernel generation as bf16 HMMA GEMMs.
//   l = 32u + v, u in [0,128), v in [0,32)
//   K[h,l] = sum_{m<64} F[u,m] * G[v,m]
// R9: CTA = half channel (64 rows, TPB=64, grid 2048) -> 8 CTAs/SM, no idle
// prologue warps. Tables stored as float2 with 16B-aligned rows -> fragment
// table reads are LDS.128 (64 LDS.32 -> 16 LDS.128 per thread).
// Split arithmetic / B layout / MMA identical to R8 (rel_err 2.96e-5).

#define HN  1024
#define NM  32
#define LL  4096
#define TPB 64

__device__ __forceinline__ uint32_t pack_hi16(float a, float b) {
    uint32_t r;
    asm("prmt.b32 %0, %1, %2, 0x7632;"
        : "=r"(r) : "r"(__float_as_uint(a)), "r"(__float_as_uint(b)));
    return r;
}

__device__ __forceinline__ void mma16816(float* c, uint32_t a0, uint32_t a1,
                                         uint32_t a2, uint32_t a3,
                                         uint32_t b0, uint32_t b1) {
    asm volatile(
        "mma.sync.aligned.m16n8k16.row.col.f32.bf16.bf16.f32 "
        "{%0,%1,%2,%3}, {%4,%5,%6,%7}, {%8,%9}, {%0,%1,%2,%3};"
        : "+f"(c[0]), "+f"(c[1]), "+f"(c[2]), "+f"(c[3])
        : "r"(a0), "r"(a1), "r"(a2), "r"(a3), "r"(b0), "r"(b1));
}

struct Cx { float r, i; };
__device__ __forceinline__ Cx cmul(Cx a, Cx b) {
    return { a.r * b.r - a.i * b.i, a.r * b.i + a.i * b.r };
}
__device__ __forceinline__ Cx csq(Cx a) {
    return { a.r * a.r - a.i * a.i, 2.0f * a.r * a.i };
}

// B granule word index (unchanged from R8): reader granule (ks,h) at lane is LDS.128.
#define BW(v, wc) (((wc) >> 2) * 128 + ((((v) & 7) << 2) + ((wc) & 3)) * 4 + ((v) >> 3))

__global__ void __launch_bounds__(TPB, 8)
s4d_hmma_kernel(const float* __restrict__ log_dt,      // (H)
                const float* __restrict__ C_real,      // (1,H,NM,2)
                const float* __restrict__ log_A_real,  // (H,NM)
                const float* __restrict__ A_imag,      // (H,NM)
                float* __restrict__ out)               // (1,H,L)
{
    __shared__ __align__(16) uint16_t sBh[2048], sBl[2048];  // 4 KB each
    __shared__ __align__(16) float2 T2c[16][34];             // Z^b, Z = dA^32 (row 272B, 16B-mult)
    __shared__ __align__(16) float2 Uc[4][34];               // 2*dC * Z16^(a) for this half

    const int h    = blockIdx.x >> 1;
    const int half = blockIdx.x & 1;
    const int t    = threadIdx.x;
    const int wid  = t >> 5;
    const int lane = t & 31;

    // ---- Prologue: warp0 -> tables, warp1 -> B tile
    {
        const int m = lane;
        const float dt  = expf(log_dt[h]);
        const float Aor = -expf(log_A_real[h * NM + m]);
        const float Aoi = A_imag[h * NM + m];
        const float dtAr = Aor * dt, dtAi = Aoi * dt;
        const float denr = 1.0f - 0.5f * dtAr;
        const float deni = -0.5f * dtAi;
        const float inv  = 1.0f / (denr * denr + deni * deni);
        const float numr = 1.0f + 0.5f * dtAr;
        const float numi = 0.5f * dtAi;
        const Cx dA = { (numr * denr + numi * deni) * inv,
                        (numi * denr - numr * deni) * inv };

        if (wid == 1) {
            // B tile: G[v][m] = Re(dA^v), G[v][32+m] = -Im(dA^v); hi/lo split.
            const int wcR = m >> 1, wcI = 16 + (m >> 1), hw = m & 1;
            Cx w = {1.0f, 0.0f};
            #pragma unroll 1
            for (int v = 0; v < 32; ++v) {
                const int iR = (BW(v, wcR) << 1) + hw;
                const int iI = (BW(v, wcI) << 1) + hw;
                const uint32_t xr = __float_as_uint(w.r);
                const float hr = __uint_as_float(xr & 0xFFFF0000u);
                sBh[iR] = (uint16_t)(xr >> 16);
                sBl[iR] = (uint16_t)(__float_as_uint(w.r - hr) >> 16);
                const float niv = -w.i;
                const uint32_t xi = __float_as_uint(niv);
                const float hi = __uint_as_float(xi & 0xFFFF0000u);
                sBh[iI] = (uint16_t)(xi >> 16);
                sBl[iI] = (uint16_t)(__float_as_uint(niv - hi) >> 16);
                w = cmul(w, dA);
            }
        } else {
            const float Br = dt * denr * inv;
            const float Bi = -dt * deni * inv;
            const float Cr = C_real[(h * NM + m) * 2 + 0];
            const float Ci = C_real[(h * NM + m) * 2 + 1];
            const Cx dC = { 2.0f * (Cr * Br - Ci * Bi),     // factor 2 baked in
                            2.0f * (Cr * Bi + Ci * Br) };
            // Z = dA^32; T2[b] = Z^b
            Cx z = dA;
            #pragma unroll
            for (int j = 0; j < 5; ++j) z = csq(z);
            Cx p = {1.0f, 0.0f};
            #pragma unroll
            for (int b = 0; b < 16; ++b) {
                T2c[b][m] = make_float2(p.r, p.i);
                p = cmul(p, z);
            }
            const Cx z16 = p;                // dA^512
            // U rows for THIS half: a_glob = 4*half + a'; start = dC * Z16^(4*half)
            Cx y = half ? cmul(dC, csq(csq(z16))) : dC;
            #pragma unroll
            for (int a = 0; a < 4; ++a) {
                Uc[a][m] = make_float2(y.r, y.i);
                y = cmul(y, z16);
            }
        }
    }
    __syncthreads();

    // ---- Mainloop: warp wid -> rows [64*half + 32*wid, +32)
    const int gid = lane >> 2;
    const int tig = lane & 3;

    float acc[2][4][4] = {};

    const float4* B4h = reinterpret_cast<const float4*>(sBh);
    const float4* B4l = reinterpret_cast<const float4*>(sBl);

    #pragma unroll
    for (int kq = 0; kq < 2; ++kq) {
        // modes for this thread: n0, n0+1, n0+8, n0+9
        const int n0 = 16 * kq + 2 * tig;

        // T2 rows gid (r0) and gid+8 (r1): two adjacent complexes per LDS.128
        const float4 tg01 = *reinterpret_cast<const float4*>(&T2c[gid][n0]);
        const float4 tg89 = *reinterpret_cast<const float4*>(&T2c[gid][n0 + 8]);
        const float4 th01 = *reinterpret_cast<const float4*>(&T2c[gid + 8][n0]);
        const float4 th89 = *reinterpret_cast<const float4*>(&T2c[gid + 8][n0 + 8]);
        const float tg_r[4] = { tg01.x, tg01.z, tg89.x, tg89.z };
        const float tg_i[4] = { tg01.y, tg01.w, tg89.y, tg89.w };
        const float th_r[4] = { th01.x, th01.z, th89.x, th89.z };
        const float th_i[4] = { th01.y, th01.w, th89.y, th89.w };

        // A fragments: [ksel(Re/Im)][hi/lo][mt][reg]
        uint32_t Af[2][2][2][4];
        #pragma unroll
        for (int mt = 0; mt < 2; ++mt) {
            const int aLoc = 2 * wid + mt;
            const float4 u01 = *reinterpret_cast<const float4*>(&Uc[aLoc][n0]);
            const float4 u89 = *reinterpret_cast<const float4*>(&Uc[aLoc][n0 + 8]);
            const float u_r[4] = { u01.x, u01.z, u89.x, u89.z };
            const float u_i[4] = { u01.y, u01.w, u89.y, u89.w };
            float pr0[4], pi0[4], pr1[4], pi1[4];
            #pragma unroll
            for (int j = 0; j < 4; ++j) {
                pr0[j] = u_r[j] * tg_r[j] - u_i[j] * tg_i[j];
                pi0[j] = u_r[j] * tg_i[j] + u_i[j] * tg_r[j];
                pr1[j] = u_r[j] * th_r[j] - u_i[j] * th_i[j];
                pi1[j] = u_r[j] * th_i[j] + u_i[j] * th_r[j];
            }
            #pragma unroll
            for (int cp = 0; cp < 2; ++cp) {
                const int j0 = cp * 2, j1 = cp * 2 + 1;
                Af[0][0][mt][cp * 2 + 0] = pack_hi16(pr0[j0], pr0[j1]);
                Af[0][0][mt][cp * 2 + 1] = pack_hi16(pr1[j0], pr1[j1]);
                Af[1][0][mt][cp * 2 + 0] = pack_hi16(pi0[j0], pi0[j1]);
                Af[1][0][mt][cp * 2 + 1] = pack_hi16(pi1[j0], pi1[j1]);
                const float d00 = pr0[j0] - __uint_as_float(__float_as_uint(pr0[j0]) & 0xFFFF0000u);
                const float d01 = pr0[j1] - __uint_as_float(__float_as_uint(pr0[j1]) & 0xFFFF0000u);
                const float d10 = pr1[j0] - __uint_as_float(__float_as_uint(pr1[j0]) & 0xFFFF0000u);
                const float d11 = pr1[j1] - __uint_as_float(__float_as_uint(pr1[j1]) & 0xFFFF0000u);
                Af[0][1][mt][cp * 2 + 0] = pack_hi16(d00, d01);
                Af[0][1][mt][cp * 2 + 1] = pack_hi16(d10, d11);
                const float e00 = pi0[j0] - __uint_as_float(__float_as_uint(pi0[j0]) & 0xFFFF0000u);
                const float e01 = pi0[j1] - __uint_as_float(__float_as_uint(pi0[j1]) & 0xFFFF0000u);
                const float e10 = pi1[j0] - __uint_as_float(__float_as_uint(pi1[j0]) & 0xFFFF0000u);
                const float e11 = pi1[j1] - __uint_as_float(__float_as_uint(pi1[j1]) & 0xFFFF0000u);
                Af[1][1][mt][cp * 2 + 0] = pack_hi16(e00, e01);
                Af[1][1][mt][cp * 2 + 1] = pack_hi16(e10, e11);
            }
        }

        // MMAs: ksel 0 -> ks=kq (Re cols), ksel 1 -> ks=kq+2 (Im cols)
        #pragma unroll
        for (int ksel = 0; ksel < 2; ++ksel) {
            const int ks = kq + 2 * ksel;
            const float4 bh0 = B4h[(ks * 2 + 0) * 32 + lane];
            const float4 bh1 = B4h[(ks * 2 + 1) * 32 + lane];
            const float4 bl0 = B4l[(ks * 2 + 0) * 32 + lane];
            const float4 bl1 = B4l[(ks * 2 + 1) * 32 + lane];
            const uint32_t* h0 = reinterpret_cast<const uint32_t*>(&bh0);
            const uint32_t* h1 = reinterpret_cast<const uint32_t*>(&bh1);
            const uint32_t* l0 = reinterpret_cast<const uint32_t*>(&bl0);
            const uint32_t* l1 = reinterpret_cast<const uint32_t*>(&bl1);
            #pragma unroll
            for (int mt = 0; mt < 2; ++mt) {
                const uint32_t* ah = Af[ksel][0][mt];
                const uint32_t* al = Af[ksel][1][mt];
                #pragma unroll
                for (int nt = 0; nt < 4; ++nt) {
                    mma16816(acc[mt][nt], ah[0], ah[1], ah[2], ah[3], h0[nt], h1[nt]); // Fh*Gh
                    mma16816(acc[mt][nt], ah[0], ah[1], ah[2], ah[3], l0[nt], l1[nt]); // Fh*Gl
                    mma16816(acc[mt][nt], al[0], al[1], al[2], al[3], h0[nt], h1[nt]); // Fl*Gh
                }
            }
        }
    }

    // ---- Epilogue
    float* __restrict__ o = out + (size_t)h * LL;
    const int r0 = 64 * half + 32 * wid;
    #pragma unroll
    for (int mt = 0; mt < 2; ++mt) {
        const int u0 = r0 + mt * 16 + gid;
        #pragma unroll
        for (int nt = 0; nt < 4; ++nt) {
            const int v = nt * 8 + tig * 2;
            *reinterpret_cast<float2*>(o + (size_t)u0 * 32 + v) =
                make_float2(acc[mt][nt][0], acc[mt][nt][1]);
            *reinterpret_cast<float2*>(o + (size_t)(u0 + 8) * 32 + v) =
                make_float2(acc[mt][nt][2], acc[mt][nt][3]);
        }
    }
}

extern "C" void kernel_launch(void* const* d_in, const int* in_sizes, int n_in,
                              void* d_out, int out_size) {
    const float* log_dt     = (const float*)d_in[0];
    const float* C_real     = (const float*)d_in[1];
    const float* log_A_real = (const float*)d_in[2];
    const float* A_imag     = (const float*)d_in[3];
    float* out = (float*)d_out;
    s4d_hmma_kernel<<<HN * 2, TPB>>>(log_dt, C_real, log_A_real, A_imag, out);
}